// round 11
// baseline (speedup 1.0000x reference)
#include <cuda_runtime.h>
#include <cuda_fp16.h>
#include <cstdint>

// Problem constants: D=128, T=17, N=87381
#define DD 128
#define TMAXTAGS 32
#define CAP 87424
#define TILE_M 32

// Scratch (static device globals; zero-initialized at module load)
__device__ int g_count[TMAXTAGS];
__device__ int g_done[TMAXTAGS];
__device__ int g_idx[TMAXTAGS * CAP];

// ---------------------------------------------------------------------------
// PTX helpers
// ---------------------------------------------------------------------------
__device__ __forceinline__ uint32_t smem_u32(const void* p) {
    uint32_t a;
    asm("{ .reg .u64 t; cvta.to.shared.u64 t, %1; cvt.u32.u64 %0, t; }"
        : "=r"(a) : "l"(p));
    return a;
}
__device__ __forceinline__ void ldsm_x4(uint32_t* r, uint32_t addr) {
    asm volatile("ldmatrix.sync.aligned.m8n8.x4.shared.b16 {%0,%1,%2,%3}, [%4];"
                 : "=r"(r[0]), "=r"(r[1]), "=r"(r[2]), "=r"(r[3]) : "r"(addr));
}
__device__ __forceinline__ void mma16816(float* d, const uint32_t* a, const uint32_t* b) {
    asm volatile(
        "mma.sync.aligned.m16n8k16.row.col.f32.f16.f16.f32 "
        "{%0,%1,%2,%3}, {%4,%5,%6,%7}, {%8,%9}, {%0,%1,%2,%3};"
        : "+f"(d[0]), "+f"(d[1]), "+f"(d[2]), "+f"(d[3])
        : "r"(a[0]), "r"(a[1]), "r"(a[2]), "r"(a[3]), "r"(b[0]), "r"(b[1]));
}

// ---------------------------------------------------------------------------
// Shared memory. Row stride 272B (128 fp16 + 8 pad): every quarter-warp
// ldmatrix phase addresses 8 distinct 16B bank-quads -> conflict-free.
// CTA covers 64 of the 128 output cols (half of W) and 32 node rows.
// ---------------------------------------------------------------------------
#define RSTRIDE 272
#define OFF_WHI   0                         // 64*272 = 17408
#define OFF_WLO   17408
#define OFF_A     34816                     // 32*272 = 8704
#define OFF_BIAS  43520                     // 64 f32
#define OFF_WMAX  43776                     // 64 f32
#define SMEM_TOTAL 44032

extern __shared__ char s_raw[];

// Convert float4 -> 4 fp16, store 8B into padded tile.
__device__ __forceinline__ void cvt_store1(char* dst, int row, int lid, float4 v) {
    __half2 p0 = __floats2half2_rn(v.x, v.y);
    __half2 p1 = __floats2half2_rn(v.z, v.w);
    uint32_t o = (uint32_t)row * RSTRIDE + (uint32_t)lid * 8;
    *(uint2*)(dst + o) = make_uint2(*(uint32_t*)&p0, *(uint32_t*)&p1);
}
// Convert float4 -> hi/lo fp16 pairs (22-bit effective), store 8B each.
__device__ __forceinline__ void cvt_store2(char* hi, char* lo, int row, int lid, float4 v) {
    __half h0 = __float2half_rn(v.x), h1 = __float2half_rn(v.y);
    __half h2 = __float2half_rn(v.z), h3 = __float2half_rn(v.w);
    __half l0 = __float2half_rn(v.x - __half2float(h0));
    __half l1 = __float2half_rn(v.y - __half2float(h1));
    __half l2 = __float2half_rn(v.z - __half2float(h2));
    __half l3 = __float2half_rn(v.w - __half2float(h3));
    uint32_t hA = ((uint32_t)__half_as_ushort(h1) << 16) | __half_as_ushort(h0);
    uint32_t hB = ((uint32_t)__half_as_ushort(h3) << 16) | __half_as_ushort(h2);
    uint32_t lA = ((uint32_t)__half_as_ushort(l1) << 16) | __half_as_ushort(l0);
    uint32_t lB = ((uint32_t)__half_as_ushort(l3) << 16) | __half_as_ushort(l2);
    uint32_t o = (uint32_t)row * RSTRIDE + (uint32_t)lid * 8;
    *(uint2*)(hi + o) = make_uint2(hA, hB);
    *(uint2*)(lo + o) = make_uint2(lA, lB);
}

// ---------------------------------------------------------------------------
// Kernel 1: zero output + block-aggregated bucketing.
// ---------------------------------------------------------------------------
__global__ void compact_kernel(const int* __restrict__ tag, int N,
                               float* __restrict__ out) {
    __shared__ int s_cnt[TMAXTAGS];
    __shared__ int s_base[TMAXTAGS];
    const int tid = threadIdx.x;
    if (blockIdx.x == 0 && tid < DD) out[tid] = 0.0f;
    if (tid < TMAXTAGS) s_cnt[tid] = 0;
    __syncthreads();

    const int n = blockIdx.x * blockDim.x + tid;
    int t = 0, p = 0;
    if (n < N) {
        t = tag[n];
        p = atomicAdd(&s_cnt[t], 1);
    }
    __syncthreads();
    if (tid < TMAXTAGS && s_cnt[tid] > 0)
        s_base[tid] = atomicAdd(&g_count[tid], s_cnt[tid]);
    __syncthreads();
    if (n < N) g_idx[t * CAP + s_base[t] + p] = n;
}

// ---------------------------------------------------------------------------
// Kernel 2: 2-term fp16 HMMA GEMM + max reduce with W fragments hoisted
// into registers (loaded once per block), register-prefetch A pipeline.
// grid = (G, 2T): y encodes (tag, col-half). 256 threads, 3 CTAs/SM.
// Warp w owns cols hf*64 + w*8 .. +7, all 32 tile rows.
// ---------------------------------------------------------------------------
__global__ __launch_bounds__(256, 3) void gemm_max_kernel(
    const float* __restrict__ emb, const float* __restrict__ W,
    const float* __restrict__ b, float* __restrict__ out, int G)
{
    char* smem = s_raw;
    const int t   = blockIdx.y >> 1;
    const int hf  = blockIdx.y & 1;
    const int tid = threadIdx.x;
    const int wid = tid >> 5;
    const int lid = tid & 31;
    const int cnt = g_count[t];

    const bool active = (long)blockIdx.x * TILE_M < cnt;  // block-uniform
    if (active) {
        const uint32_t sb = smem_u32(smem);
        const int* idx_t = &g_idx[t * CAP];

        // --- Prefetch tile 0 (warp rows wid, wid+8, wid+16, wid+24) ---
        float4 pf[4];
        {
            const int base = blockIdx.x * TILE_M;
            #pragma unroll
            for (int i = 0; i < 4; i++) {
                int p = base + wid + i * 8;
                int idx = __ldg(idx_t + min(p, cnt - 1));
                pf[i] = *(const float4*)(emb + (size_t)idx * DD + lid * 4);
            }
        }

        // --- Prologue: convert this col-half of W[t] into Whi/Wlo, bias ---
        const float* Wt = W + (size_t)t * DD * DD + (size_t)hf * 64 * DD;
        for (int r = wid; r < 64; r += 8) {
            float4 v = *(const float4*)(Wt + r * DD + lid * 4);
            cvt_store2(smem + OFF_WHI, smem + OFF_WLO, r, lid, v);
        }
        if (tid < 64)
            ((float*)(smem + OFF_BIAS))[tid] = b[t * DD + hf * 64 + tid];
        __syncthreads();   // W tiles visible before the register hoist

        // --- Hoist this warp's B fragments (8 cols x K=128, hi+lo) ---
        // x4 packs two K-steps: quads -> (kkE,h0),(kkE,h1),(kkO,h0),(kkO,h1)
        uint32_t bh[16], bl[16];
        {
            const uint32_t offB = (uint32_t)(wid * 8 + (lid & 7)) * RSTRIDE
                                + (uint32_t)((lid >> 3) & 1) * 16
                                + (uint32_t)(lid >> 4) * 32;
            #pragma unroll
            for (int j = 0; j < 4; j++) {
                ldsm_x4(bh + j * 4, sb + OFF_WHI + offB + j * 64);
                ldsm_x4(bl + j * 4, sb + OFF_WLO + offB + j * 64);
            }
        }

        // A ldmatrix offset: rows (mf*16 + lid&15), k-half (lid>>4)
        const uint32_t aT = sb + OFF_A
                          + (uint32_t)(lid & 15) * RSTRIDE
                          + (uint32_t)(lid >> 4) * 16;

        float mx0 = __int_as_float(0xff800000);
        float mx1 = __int_as_float(0xff800000);

        for (int tile = blockIdx.x; tile * TILE_M < cnt; tile += G) {
            const int base = tile * TILE_M;

            // Store prefetched rows for THIS tile into A smem
            #pragma unroll
            for (int i = 0; i < 4; i++)
                cvt_store1(smem + OFF_A, wid + i * 8, lid, pf[i]);
            __syncthreads();

            // Prefetch NEXT tile; lands during the MMA loop
            {
                const int nbase = (tile + G) * TILE_M;
                if (nbase < cnt) {
                    #pragma unroll
                    for (int i = 0; i < 4; i++) {
                        int p = nbase + wid + i * 8;
                        int idx = __ldg(idx_t + min(p, cnt - 1));
                        pf[i] = *(const float4*)(emb + (size_t)idx * DD + lid * 4);
                    }
                }
            }

            float acc[8];
            #pragma unroll
            for (int i = 0; i < 8; i++) acc[i] = 0.0f;

            // Mainloop: only A is loaded; B lives in registers.
            #pragma unroll
            for (int kk = 0; kk < 8; kk++) {
                uint32_t a0[4], a1[4];
                ldsm_x4(a0, aT + kk * 32);
                ldsm_x4(a1, aT + 16 * RSTRIDE + kk * 32);
                mma16816(acc + 0, a0, bh + kk * 2);
                mma16816(acc + 0, a0, bl + kk * 2);
                mma16816(acc + 4, a1, bh + kk * 2);
                mma16816(acc + 4, a1, bl + kk * 2);
            }

            // Masked running max (rows mf*16 + lid>>2 and +8)
            {
                const int r0 = base + (lid >> 2);
                const bool v00 = r0      < cnt, v01 = r0 + 8  < cnt;
                const bool v10 = r0 + 16 < cnt, v11 = r0 + 24 < cnt;
                float m0 = __int_as_float(0xff800000);
                float m1 = __int_as_float(0xff800000);
                if (v00) { m0 = fmaxf(m0, acc[0]); m1 = fmaxf(m1, acc[1]); }
                if (v01) { m0 = fmaxf(m0, acc[2]); m1 = fmaxf(m1, acc[3]); }
                if (v10) { m0 = fmaxf(m0, acc[4]); m1 = fmaxf(m1, acc[5]); }
                if (v11) { m0 = fmaxf(m0, acc[6]); m1 = fmaxf(m1, acc[7]); }
                mx0 = fmaxf(mx0, m0);
                mx1 = fmaxf(mx1, m1);
            }
            __syncthreads();   // all A reads done before next tile's stores
        }

        // --- Reduce across lanes sharing the same cols (lid&3 groups) ---
        #pragma unroll
        for (int s = 4; s < 32; s <<= 1) {
            mx0 = fmaxf(mx0, __shfl_xor_sync(0xFFFFFFFFu, mx0, s));
            mx1 = fmaxf(mx1, __shfl_xor_sync(0xFFFFFFFFu, mx1, s));
        }
        float* wm = (float*)(smem + OFF_WMAX);
        if (lid < 4) {
            wm[wid * 8 + lid * 2 + 0] = mx0;
            wm[wid * 8 + lid * 2 + 1] = mx1;
        }
        __syncthreads();

        if (tid < 64) {
            float m = wm[tid];
            float bias = ((float*)(smem + OFF_BIAS))[tid];
            float y = fmaxf(m + bias, 0.0f);   // >=0 -> int-bit atomicMax valid
            atomicMax((int*)out + hf * 64 + tid, __float_as_int(y));
        }
    }

    // End ticket: last block of this tag (2G blocks) resets counters.
    if (tid == 0) {
        __threadfence();
        int v = atomicAdd(&g_done[t], 1);
        if (v == 2 * (int)gridDim.x - 1) {
            g_done[t] = 0;
            g_count[t] = 0;
        }
    }
}

// ---------------------------------------------------------------------------
// Launch
// ---------------------------------------------------------------------------
extern "C" void kernel_launch(void* const* d_in, const int* in_sizes, int n_in,
                              void* d_out, int out_size) {
    const float* emb = (const float*)d_in[0];
    const float* W   = (const float*)d_in[1];
    const float* b   = (const float*)d_in[2];
    const int*   tag = (const int*)d_in[3];
    // parent/depth irrelevant: root z == elementwise max over all nodes of
    // relu(W[tag] @ emb + b); relu>=0 makes 0 the max identity.

    float* out = (float*)d_out;
    const int N = in_sizes[3];
    const int T = in_sizes[2] / DD;

    static bool attr_set = false;
    if (!attr_set) {
        cudaFuncSetAttribute(gemm_max_kernel,
                             cudaFuncAttributeMaxDynamicSharedMemorySize,
                             SMEM_TOTAL);
        attr_set = true;
    }

    compact_kernel<<<(N + 511) / 512, 512>>>(tag, N, out);

    const int G = 13;  // 13 * 34 = 442 CTAs <= 444 slots (3/SM): single wave
    dim3 grid(G, 2 * T);
    gemm_max_kernel<<<grid, 256, SMEM_TOTAL>>>(emb, W, b, out, G);
}